// round 2
// baseline (speedup 1.0000x reference)
#include <cuda_runtime.h>
#include <cstdint>

#define NN 100000
#define NE 1600000
#define NCH ((NN + 255) / 256)   // 391 chunks of 256
#define NT 4                     // nodes per warp tile

// ---------------- device scratch (no allocs allowed) ----------------
__device__ int   g_deg[NN];
__device__ int   g_off[NN + 1];
__device__ int   g_cur[NN];
__device__ float g_inv[NN];
__device__ int   g_csr[NE];
__device__ int   g_part[NCH];
__device__ float g_h0[(size_t)NN * 64];
__device__ float g_h1[(size_t)NN * 64];

// ---------------- f32x2 helpers (Blackwell packed fp32) ----------------
__device__ __forceinline__ unsigned long long pk2(float x, float y) {
    unsigned long long r;
    asm("mov.b64 %0,{%1,%2};" : "=l"(r) : "f"(x), "f"(y));
    return r;
}
__device__ __forceinline__ void upk2(unsigned long long v, float &x, float &y) {
    asm("mov.b64 {%0,%1},%2;" : "=f"(x), "=f"(y) : "l"(v));
}
__device__ __forceinline__ void fma2(unsigned long long &d, unsigned long long w, unsigned long long a) {
    asm("fma.rn.f32x2 %0,%1,%2,%0;" : "+l"(d) : "l"(w), "l"(a));
}

// ---------------- CSR construction ----------------
__global__ void k_zero_deg() {
    int i = blockIdx.x * blockDim.x + threadIdx.x;
    if (i < NN) g_deg[i] = 0;
}

__global__ void k_count(const int* __restrict__ dst) {
    int e = blockIdx.x * blockDim.x + threadIdx.x;
    if (e < NE) atomicAdd(&g_deg[dst[e]], 1);
}

__global__ void k_chunksum() {
    __shared__ int s[256];
    int t = threadIdx.x;
    int idx = blockIdx.x * 256 + t;
    s[t] = (idx < NN) ? g_deg[idx] : 0;
    __syncthreads();
    for (int o = 128; o > 0; o >>= 1) {
        if (t < o) s[t] += s[t + o];
        __syncthreads();
    }
    if (t == 0) g_part[blockIdx.x] = s[0];
}

__global__ void k_scanpart() {
    __shared__ int s[512];
    int t = threadIdx.x;
    int v = (t < NCH) ? g_part[t] : 0;
    s[t] = v;
    __syncthreads();
    for (int d = 1; d < 512; d <<= 1) {
        int tmp = (t >= d) ? s[t - d] : 0;
        __syncthreads();
        s[t] += tmp;
        __syncthreads();
    }
    if (t < NCH) g_part[t] = s[t] - v;   // exclusive
}

__global__ void k_offsets() {
    __shared__ int s[256];
    int t = threadIdx.x;
    int idx = blockIdx.x * 256 + t;
    int d = (idx < NN) ? g_deg[idx] : 0;
    s[t] = d;
    __syncthreads();
    for (int o = 1; o < 256; o <<= 1) {
        int tmp = (t >= o) ? s[t - o] : 0;
        __syncthreads();
        s[t] += tmp;
        __syncthreads();
    }
    int excl = s[t] - d;
    int off = g_part[blockIdx.x] + excl;
    if (idx < NN) {
        g_off[idx] = off;
        g_cur[idx] = off;
        int dd = d > 1 ? d : 1;
        g_inv[idx] = 1.0f / (float)dd;
    }
    if (idx == NN - 1) g_off[NN] = off + d;
}

__global__ void k_fill(const int* __restrict__ src, const int* __restrict__ dst) {
    int e = blockIdx.x * blockDim.x + threadIdx.x;
    if (e < NE) {
        int d = dst[e];
        int p = atomicAdd(&g_cur[d], 1);
        g_csr[p] = src[e];
    }
}

// ---------------- feature_pre: h0 = x @ W_pre.T + b_pre ----------------
// x: [NN,128], W: [64,128], out: [NN,64]
__global__ __launch_bounds__(256) void k_pre(const float* __restrict__ x,
                                             const float* __restrict__ W,
                                             const float* __restrict__ b,
                                             float* __restrict__ hout) {
    extern __shared__ float sm[];
    float* sW = sm;                  // [128][64]: sW[k*64+j] = W[j*128+k]
    float* sX = sm + 128 * 64;       // [8 warps][NT][128]
    for (int i = threadIdx.x; i < 128 * 64; i += blockDim.x) {
        int j = i >> 7, k = i & 127;
        sW[k * 64 + j] = W[i];
    }
    __syncthreads();
    const unsigned long long* sW2 = (const unsigned long long*)sW;
    int warp = threadIdx.x >> 5, lane = threadIdx.x & 31;
    float2 b2 = ((const float2*)b)[lane];
    float* sXw = sX + warp * (NT * 128);
    int gwarp = blockIdx.x * 8 + warp;
    int nwarp = gridDim.x * 8;
    for (int g = gwarp; g < NN / NT; g += nwarp) {
        int v0 = g * NT;
#pragma unroll
        for (int n = 0; n < NT; n++) {
            float4 xv = *(const float4*)(x + (size_t)(v0 + n) * 128 + lane * 4);
            *(float4*)(sXw + n * 128 + lane * 4) = xv;
        }
        __syncwarp();
        unsigned long long acc[NT];
#pragma unroll
        for (int n = 0; n < NT; n++) acc[n] = pk2(b2.x, b2.y);
        for (int k = 0; k < 128; k += 4) {
            unsigned long long w0 = sW2[(k + 0) * 32 + lane];
            unsigned long long w1 = sW2[(k + 1) * 32 + lane];
            unsigned long long w2 = sW2[(k + 2) * 32 + lane];
            unsigned long long w3 = sW2[(k + 3) * 32 + lane];
#pragma unroll
            for (int n = 0; n < NT; n++) {
                float4 a = *(const float4*)(sXw + n * 128 + k);
                fma2(acc[n], w0, pk2(a.x, a.x));
                fma2(acc[n], w1, pk2(a.y, a.y));
                fma2(acc[n], w2, pk2(a.z, a.z));
                fma2(acc[n], w3, pk2(a.w, a.w));
            }
        }
#pragma unroll
        for (int n = 0; n < NT; n++) {
            float ox, oy;
            upk2(acc[n], ox, oy);
            *(float2*)(hout + (size_t)(v0 + n) * 64 + lane * 2) = make_float2(ox, oy);
        }
        __syncwarp();
    }
}

// ---------------- SAGE layer (64 -> 64), optional ReLU ----------------
// hout[v] = act( Wl @ (inv_deg[v] * sum_{u in N(v)} hin[u]) + bl + Wr @ hin[v] )
template <bool RELU>
__global__ __launch_bounds__(256) void k_layer(const float* __restrict__ hin,
                                               float* __restrict__ hout,
                                               const float* __restrict__ Wl,
                                               const float* __restrict__ bl,
                                               const float* __restrict__ Wr) {
    extern __shared__ float sm[];
    float* sWl = sm;            // [64][64] transposed
    float* sWr = sm + 4096;
    float* sV  = sm + 8192;     // [8 warps][NT][128] : agg(64) | self(64)
    for (int i = threadIdx.x; i < 4096; i += blockDim.x) {
        int j = i >> 6, k = i & 63;
        sWl[k * 64 + j] = Wl[i];
        sWr[k * 64 + j] = Wr[i];
    }
    __syncthreads();
    const unsigned long long* sWl2 = (const unsigned long long*)sWl;
    const unsigned long long* sWr2 = (const unsigned long long*)sWr;
    int warp = threadIdx.x >> 5, lane = threadIdx.x & 31;
    float2 b2 = ((const float2*)bl)[lane];
    float* sVw = sV + warp * (NT * 128);
    int gwarp = blockIdx.x * 8 + warp;
    int nwarp = gridDim.x * 8;
    for (int g = gwarp; g < NN / NT; g += nwarp) {
        int v0 = g * NT;
#pragma unroll
        for (int n = 0; n < NT; n++) {
            int v = v0 + n;
            int s = g_off[v], e = g_off[v + 1];
            float ax = 0.f, ay = 0.f;
            int base = s;
            while (base < e) {
                int m = e - base;
                if (m > 32) m = 32;
                int sv = (base + lane < e) ? g_csr[base + lane] : 0;
                int q = 0;
                for (; q + 4 <= m; q += 4) {
                    int u0 = __shfl_sync(0xffffffffu, sv, q);
                    int u1 = __shfl_sync(0xffffffffu, sv, q + 1);
                    int u2 = __shfl_sync(0xffffffffu, sv, q + 2);
                    int u3 = __shfl_sync(0xffffffffu, sv, q + 3);
                    float2 h0 = *(const float2*)(hin + (size_t)u0 * 64 + lane * 2);
                    float2 h1 = *(const float2*)(hin + (size_t)u1 * 64 + lane * 2);
                    float2 h2 = *(const float2*)(hin + (size_t)u2 * 64 + lane * 2);
                    float2 h3 = *(const float2*)(hin + (size_t)u3 * 64 + lane * 2);
                    ax += (h0.x + h1.x) + (h2.x + h3.x);
                    ay += (h0.y + h1.y) + (h2.y + h3.y);
                }
                for (; q < m; q++) {
                    int u = __shfl_sync(0xffffffffu, sv, q);
                    float2 h = *(const float2*)(hin + (size_t)u * 64 + lane * 2);
                    ax += h.x;
                    ay += h.y;
                }
                base += m;
            }
            float idg = g_inv[v];
            float2 hv = *(const float2*)(hin + (size_t)v * 64 + lane * 2);
            sVw[n * 128 + lane * 2]      = ax * idg;
            sVw[n * 128 + lane * 2 + 1]  = ay * idg;
            sVw[n * 128 + 64 + lane * 2]     = hv.x;
            sVw[n * 128 + 64 + lane * 2 + 1] = hv.y;
        }
        __syncwarp();
        unsigned long long acc[NT];
#pragma unroll
        for (int n = 0; n < NT; n++) acc[n] = pk2(b2.x, b2.y);
        for (int k = 0; k < 64; k += 4) {
            unsigned long long wl0 = sWl2[(k + 0) * 32 + lane];
            unsigned long long wl1 = sWl2[(k + 1) * 32 + lane];
            unsigned long long wl2 = sWl2[(k + 2) * 32 + lane];
            unsigned long long wl3 = sWl2[(k + 3) * 32 + lane];
            unsigned long long wr0 = sWr2[(k + 0) * 32 + lane];
            unsigned long long wr1 = sWr2[(k + 1) * 32 + lane];
            unsigned long long wr2 = sWr2[(k + 2) * 32 + lane];
            unsigned long long wr3 = sWr2[(k + 3) * 32 + lane];
#pragma unroll
            for (int n = 0; n < NT; n++) {
                float4 a  = *(const float4*)(sVw + n * 128 + k);
                float4 xx = *(const float4*)(sVw + n * 128 + 64 + k);
                fma2(acc[n], wl0, pk2(a.x, a.x));
                fma2(acc[n], wl1, pk2(a.y, a.y));
                fma2(acc[n], wl2, pk2(a.z, a.z));
                fma2(acc[n], wl3, pk2(a.w, a.w));
                fma2(acc[n], wr0, pk2(xx.x, xx.x));
                fma2(acc[n], wr1, pk2(xx.y, xx.y));
                fma2(acc[n], wr2, pk2(xx.z, xx.z));
                fma2(acc[n], wr3, pk2(xx.w, xx.w));
            }
        }
#pragma unroll
        for (int n = 0; n < NT; n++) {
            float ox, oy;
            upk2(acc[n], ox, oy);
            if (RELU) {
                ox = fmaxf(ox, 0.f);
                oy = fmaxf(oy, 0.f);
            }
            *(float2*)(hout + (size_t)(v0 + n) * 64 + lane * 2) = make_float2(ox, oy);
        }
        __syncwarp();
    }
}

// ---------------- final layer (64 -> 32) + L2 row normalize ----------------
__global__ __launch_bounds__(256) void k_layer3(const float* __restrict__ hin,
                                                float* __restrict__ out,
                                                const float* __restrict__ Wl,
                                                const float* __restrict__ bl,
                                                const float* __restrict__ Wr) {
    extern __shared__ float sm[];
    float* sWl = sm;            // [64][32] transposed
    float* sWr = sm + 2048;
    float* sV  = sm + 4096;     // [8 warps][NT][128]
    for (int i = threadIdx.x; i < 2048; i += blockDim.x) {
        int j = i >> 6, k = i & 63;
        sWl[k * 32 + j] = Wl[i];
        sWr[k * 32 + j] = Wr[i];
    }
    __syncthreads();
    int warp = threadIdx.x >> 5, lane = threadIdx.x & 31;
    float bj = bl[lane];
    float* sVw = sV + warp * (NT * 128);
    int gwarp = blockIdx.x * 8 + warp;
    int nwarp = gridDim.x * 8;
    for (int g = gwarp; g < NN / NT; g += nwarp) {
        int v0 = g * NT;
#pragma unroll
        for (int n = 0; n < NT; n++) {
            int v = v0 + n;
            int s = g_off[v], e = g_off[v + 1];
            float ax = 0.f, ay = 0.f;
            int base = s;
            while (base < e) {
                int m = e - base;
                if (m > 32) m = 32;
                int sv = (base + lane < e) ? g_csr[base + lane] : 0;
                int q = 0;
                for (; q + 4 <= m; q += 4) {
                    int u0 = __shfl_sync(0xffffffffu, sv, q);
                    int u1 = __shfl_sync(0xffffffffu, sv, q + 1);
                    int u2 = __shfl_sync(0xffffffffu, sv, q + 2);
                    int u3 = __shfl_sync(0xffffffffu, sv, q + 3);
                    float2 h0 = *(const float2*)(hin + (size_t)u0 * 64 + lane * 2);
                    float2 h1 = *(const float2*)(hin + (size_t)u1 * 64 + lane * 2);
                    float2 h2 = *(const float2*)(hin + (size_t)u2 * 64 + lane * 2);
                    float2 h3 = *(const float2*)(hin + (size_t)u3 * 64 + lane * 2);
                    ax += (h0.x + h1.x) + (h2.x + h3.x);
                    ay += (h0.y + h1.y) + (h2.y + h3.y);
                }
                for (; q < m; q++) {
                    int u = __shfl_sync(0xffffffffu, sv, q);
                    float2 h = *(const float2*)(hin + (size_t)u * 64 + lane * 2);
                    ax += h.x;
                    ay += h.y;
                }
                base += m;
            }
            float idg = g_inv[v];
            float2 hv = *(const float2*)(hin + (size_t)v * 64 + lane * 2);
            sVw[n * 128 + lane * 2]      = ax * idg;
            sVw[n * 128 + lane * 2 + 1]  = ay * idg;
            sVw[n * 128 + 64 + lane * 2]     = hv.x;
            sVw[n * 128 + 64 + lane * 2 + 1] = hv.y;
        }
        __syncwarp();
#pragma unroll
        for (int n = 0; n < NT; n++) {
            float o = bj;
            for (int k = 0; k < 64; k += 4) {
                float4 a  = *(const float4*)(sVw + n * 128 + k);
                float4 xx = *(const float4*)(sVw + n * 128 + 64 + k);
                o += sWl[(k + 0) * 32 + lane] * a.x;
                o += sWl[(k + 1) * 32 + lane] * a.y;
                o += sWl[(k + 2) * 32 + lane] * a.z;
                o += sWl[(k + 3) * 32 + lane] * a.w;
                o += sWr[(k + 0) * 32 + lane] * xx.x;
                o += sWr[(k + 1) * 32 + lane] * xx.y;
                o += sWr[(k + 2) * 32 + lane] * xx.z;
                o += sWr[(k + 3) * 32 + lane] * xx.w;
            }
            float ss = o * o;
#pragma unroll
            for (int off = 16; off; off >>= 1)
                ss += __shfl_xor_sync(0xffffffffu, ss, off);
            float nrm = fmaxf(sqrtf(ss), 1e-12f);
            out[(size_t)(v0 + n) * 32 + lane] = o / nrm;
        }
        __syncwarp();
    }
}

// ---------------- launch ----------------
extern "C" void kernel_launch(void* const* d_in, const int* in_sizes, int n_in,
                              void* d_out, int out_size) {
    const float* x     = (const float*)d_in[0];
    const int*   ei    = (const int*)d_in[1];
    const float* W_pre = (const float*)d_in[2];
    const float* b_pre = (const float*)d_in[3];
    const float* Wl1 = (const float*)d_in[4];
    const float* bl1 = (const float*)d_in[5];
    const float* Wr1 = (const float*)d_in[6];
    const float* Wl2 = (const float*)d_in[7];
    const float* bl2 = (const float*)d_in[8];
    const float* Wr2 = (const float*)d_in[9];
    const float* Wl3 = (const float*)d_in[10];
    const float* bl3 = (const float*)d_in[11];
    const float* Wr3 = (const float*)d_in[12];
    float* out = (float*)d_out;
    const int* src = ei;
    const int* dst = ei + NE;

    float *ph0, *ph1;
    cudaGetSymbolAddress((void**)&ph0, g_h0);
    cudaGetSymbolAddress((void**)&ph1, g_h1);

    // CSR build
    k_zero_deg<<<(NN + 255) / 256, 256>>>();
    k_count<<<(NE + 255) / 256, 256>>>(dst);
    k_chunksum<<<NCH, 256>>>();
    k_scanpart<<<1, 512>>>();
    k_offsets<<<NCH, 256>>>();
    k_fill<<<(NE + 255) / 256, 256>>>(src, dst);

    const int GRID = 592;  // 4 blocks/SM x 148 SMs target
    k_pre<<<GRID, 256, 49152>>>(x, W_pre, b_pre, ph0);
    k_layer<true><<<GRID, 256, 49152>>>(ph0, ph1, Wl1, bl1, Wr1);
    k_layer<true><<<GRID, 256, 49152>>>(ph1, ph0, Wl2, bl2, Wr2);
    k_layer3<<<GRID, 256, 32768>>>(ph0, out, Wl3, bl3, Wr3);
}